// round 4
// baseline (speedup 1.0000x reference)
#include <cuda_runtime.h>
#include <cuda_bf16.h>

#define GRIDN   32
#define NPLANE  1089        // 33*33
#define NVOL    35937       // 33^3
#define T_ROWS  48
#define NT      128

// ---------------------------------------------------------------------------
// Zero the output (harness poisons it to 0xAA; empty cells must read 0.0f).
// ---------------------------------------------------------------------------
__global__ void zero_out_kernel(float4* __restrict__ out, int n4) {
    int i = blockIdx.x * blockDim.x + threadIdx.x;
    if (i < n4) out[i] = make_float4(0.f, 0.f, 0.f, 0.f);
}

// safe_div denominator clamp, matching the reference.
__device__ __forceinline__ float safeden(float x) {
    return (fabsf(x) > 1e-12f) ? x : 1e-12f;
}

// Non-contractible dot product: guarantees bitwise-identical results for
// bitwise-identical inputs, and exact zeros when one operand is zero.
// This replicates XLA's (non-FMA) semantics for the classification values.
__device__ __forceinline__ float dot_rn(float ax, float ay, float az,
                                        float bx, float by, float bz) {
    return __fadd_rn(__fadd_rn(__fmul_rn(ax, bx), __fmul_rn(ay, by)),
                     __fmul_rn(az, bz));
}

// ---------------------------------------------------------------------------
// Point-triangle squared distance, faithful port of the reference where-stack.
// A,B,C hold (u = p - vertex, |u|^2).  Classification quantities are computed
// with non-contracted arithmetic so duplicate-vertex (degenerate) triangles
// resolve EXACTLY like the JAX reference (exact-zero propagation).
// Candidate distances are computed stably as |p - q_region|^2 and the final
// scalar selected in the reference's exact overwrite order:
// interior -> BC -> AC -> C -> AB -> B -> A  (A wins).
// ---------------------------------------------------------------------------
__device__ __forceinline__ float tri_dist_sq(float4 A, float4 B, float4 C) {
    // ab = b - a = A - B ; ac = c - a = A - C   (u-space)
    float abx = A.x - B.x, aby = A.y - B.y, abz = A.z - B.z;
    float acx = A.x - C.x, acy = A.y - C.y, acz = A.z - C.z;

    float d1 = dot_rn(abx, aby, abz, A.x, A.y, A.z);   // dot(ab, ap)
    float d2 = dot_rn(acx, acy, acz, A.x, A.y, A.z);   // dot(ac, ap)
    float d3 = dot_rn(abx, aby, abz, B.x, B.y, B.z);   // dot(ab, bp)
    float d4 = dot_rn(acx, acy, acz, B.x, B.y, B.z);   // dot(ac, bp)
    float d5 = dot_rn(abx, aby, abz, C.x, C.y, C.z);   // dot(ab, cp)
    float d6 = dot_rn(acx, acy, acz, C.x, C.y, C.z);   // dot(ac, cp)

    // Cross terms: must be exact zeros for duplicate-vertex triangles.
    float va = __fsub_rn(__fmul_rn(d3, d6), __fmul_rn(d5, d4));
    float vb = __fsub_rn(__fmul_rn(d5, d2), __fmul_rn(d1, d6));
    float vc = __fsub_rn(__fmul_rn(d1, d4), __fmul_rn(d3, d2));
    float e43 = __fsub_rn(d4, d3);
    float e56 = __fsub_rn(d5, d6);

    // ---- interior (default): diff = A - ab*v - ac*w
    float inv = __fdividef(1.f, safeden(va + vb + vc));
    float v_in = vb * inv;
    float w_in = vc * inv;
    float ix = A.x - abx * v_in - acx * w_in;
    float iy = A.y - aby * v_in - acy * w_in;
    float iz = A.z - abz * v_in - acz * w_in;
    float d = ix * ix + iy * iy + iz * iz;

    // ---- edge BC: diff = B - (B-C)*w_bc
    {
        float wbc = __fdividef(e43, safeden(e43 + e56));
        float bx = B.x - (B.x - C.x) * wbc;
        float by = B.y - (B.y - C.y) * wbc;
        float bz = B.z - (B.z - C.z) * wbc;
        float dBC = bx * bx + by * by + bz * bz;
        if ((va <= 0.f) && (e43 >= 0.f) && (e56 >= 0.f)) d = dBC;
    }
    // ---- edge AC: diff = A - ac*w_ac
    {
        float wac = __fdividef(d2, safeden(d2 - d6));
        float ax = A.x - acx * wac;
        float ay = A.y - acy * wac;
        float az = A.z - acz * wac;
        float dAC = ax * ax + ay * ay + az * az;
        if ((vb <= 0.f) && (d2 >= 0.f) && (d6 <= 0.f)) d = dAC;
    }
    // ---- vertex C
    if ((d6 >= 0.f) && (d5 <= d6)) d = C.w;
    // ---- edge AB: diff = A - ab*v_ab
    {
        float vab = __fdividef(d1, safeden(d1 - d3));
        float ax = A.x - abx * vab;
        float ay = A.y - aby * vab;
        float az = A.z - abz * vab;
        float dAB = ax * ax + ay * ay + az * az;
        if ((vc <= 0.f) && (d1 >= 0.f) && (d3 <= 0.f)) d = dAB;
    }
    // ---- vertex B
    if ((d3 >= 0.f) && (d4 <= d3)) d = B.w;
    // ---- vertex A
    if ((d1 <= 0.f) && (d2 <= 0.f)) d = A.w;

    return d;
}

// ---------------------------------------------------------------------------
// Main kernel: one thread per point.
// ---------------------------------------------------------------------------
__global__ void __launch_bounds__(NT)
pt_dist_kernel(const float* __restrict__ offset,
               const float* __restrict__ points,
               const int*   __restrict__ tri_table,
               float*       __restrict__ out,
               int n_pts)
{
    __shared__ int    tri_s[T_ROWS * 9];
    __shared__ float4 su[12 * NT];

    int tid = threadIdx.x;
    // stage tri_table, premultiplied by NT so the inner fetch is (idx + tid)
    for (int k = tid; k < T_ROWS * 9; k += NT)
        tri_s[k] = tri_table[k] * NT;
    __syncthreads();

    int i = blockIdx.x * NT + tid;
    if (i >= n_pts) return;

    float px = points[3 * i + 0];
    float py = points[3 * i + 1];
    float pz = points[3 * i + 2];

    int cx = min(max((int)floorf(px), 0), GRIDN - 1);
    int cy = min(max((int)floorf(py), 0), GRIDN - 1);
    int cz = min(max((int)floorf(pz), 0), GRIDN - 1);
    float lx = px - (float)cx;
    float ly = py - (float)cy;
    float lz = pz - (float)cz;

    int cb = cx * NPLANE + cy * 33 + cz;
    const float* o0 = offset;             // axis 0 slab
    const float* o1 = offset + NVOL;      // axis 1 slab
    const float* o2 = offset + 2 * NVOL;  // axis 2 slab

    // 12 edge offsets t_e (EDGE_BASE / EDGE_AXIS)
    float t0  = o0[cb];
    float t1  = o1[cb + NPLANE];
    float t2  = o0[cb + 33];
    float t3  = o1[cb];
    float t4  = o0[cb + 1];
    float t5  = o1[cb + NPLANE + 1];
    float t6  = o0[cb + 33 + 1];
    float t7  = o1[cb + 1];
    float t8  = o2[cb];
    float t9  = o2[cb + NPLANE];
    float t10 = o2[cb + NPLANE + 33];
    float t11 = o2[cb + 33];

    // u_e = local - v_e, w = |u_e|^2, stored as float4 per vertex per thread
    #define STORE_U(e, ux, uy, uz) do {                       \
        float _x = (ux), _y = (uy), _z = (uz);                \
        float _w = _x * _x + _y * _y + _z * _z;               \
        su[(e) * NT + tid] = make_float4(_x, _y, _z, _w);     \
    } while (0)

    STORE_U(0,  lx - t0,  ly,       lz      );
    STORE_U(1,  lx - 1.f, ly - t1,  lz      );
    STORE_U(2,  lx - t2,  ly - 1.f, lz      );
    STORE_U(3,  lx,       ly - t3,  lz      );
    STORE_U(4,  lx - t4,  ly,       lz - 1.f);
    STORE_U(5,  lx - 1.f, ly - t5,  lz - 1.f);
    STORE_U(6,  lx - t6,  ly - 1.f, lz - 1.f);
    STORE_U(7,  lx,       ly - t7,  lz - 1.f);
    STORE_U(8,  lx,       ly,       lz - t8 );
    STORE_U(9,  lx - 1.f, ly,       lz - t9 );
    STORE_U(10, lx - 1.f, ly - 1.f, lz - t10);
    STORE_U(11, lx,       ly - 1.f, lz - t11);
    #undef STORE_U

    float* outc = out + (size_t)(((cx * GRIDN) + cy) * GRIDN + cz) * T_ROWS;

    #pragma unroll 1
    for (int t = 0; t < T_ROWS; t++) {
        const int* row = tri_s + t * 9;
        float4 A0 = su[row[0] + tid];
        float4 B0 = su[row[1] + tid];
        float4 C0 = su[row[2] + tid];
        float m = tri_dist_sq(A0, B0, C0);

        float4 A1 = su[row[3] + tid];
        float4 B1 = su[row[4] + tid];
        float4 C1 = su[row[5] + tid];
        m = fminf(m, tri_dist_sq(A1, B1, C1));

        float4 A2 = su[row[6] + tid];
        float4 B2 = su[row[7] + tid];
        float4 C2 = su[row[8] + tid];
        m = fminf(m, tri_dist_sq(A2, B2, C2));

        atomicAdd(outc + t, m);
    }
}

// ---------------------------------------------------------------------------
// Launch wrapper (graph-capturable: kernel launches only, no allocs/syncs)
// ---------------------------------------------------------------------------
extern "C" void kernel_launch(void* const* d_in, const int* in_sizes, int n_in,
                              void* d_out, int out_size) {
    const float* offset    = (const float*)d_in[0];   // (3,33,33,33) fp32
    const float* points    = (const float*)d_in[1];   // (131072,3)   fp32
    const int*   tri_table = (const int*)  d_in[2];   // (48,3,3)     int32
    float* out = (float*)d_out;                       // (32768,48)   fp32

    int n_pts = in_sizes[1] / 3;

    int n4 = out_size / 4;
    zero_out_kernel<<<(n4 + 255) / 256, 256>>>((float4*)out, n4);

    int blocks = (n_pts + NT - 1) / NT;
    pt_dist_kernel<<<blocks, NT>>>(offset, points, tri_table, out, n_pts);
}